// round 14
// baseline (speedup 1.0000x reference)
#include <cuda_runtime.h>

// Problem constants
// B=256, L=64, D=1024, H=16 (HD=64), HG=8 (HDG=128), MAXREL=32
// M = B*L = 16384 tokens. All 8 GEMMs are 16384 x 1024 x 1024.

constexpr int   GEMM_K = 1024;
constexpr int   GEMM_N = 1024;
constexpr size_t ELEMS = 16777216ull;   // B*L*D = 16384*1024

// Scratch: 9 token-matrices (qL,kL,vL,qG,kG,vG,locO,glbO,cmb)
__device__ float g_scratch[9 * ELEMS];

// ---------------------------------------------------------------------------
// Generic SGEMM:  C[m,n] = alpha * ( sum_k A[m,k]*W[n,k] + bias[n] ) + beta*Add[m,n]
// A: [16384,1024] row-major, W: [1024,1024] row-major (used transposed).
// Block tile 128x128, K-tile 16, 8x8 per-thread micro-tile, 256 threads.
// ---------------------------------------------------------------------------
__global__ __launch_bounds__(256)
void sgemm_kernel(const float* __restrict__ A, const float* __restrict__ W,
                  const float* __restrict__ bias, const float* __restrict__ Add,
                  float* __restrict__ C, float alpha, float beta)
{
    __shared__ float As[16][132];
    __shared__ float Bs[16][132];

    const int tid = threadIdx.x;
    const int bm  = blockIdx.y * 128;
    const int bn  = blockIdx.x * 128;

    const int lr = tid >> 2;          // 0..63  (load row)
    const int lc = (tid & 3) << 2;    // 0,4,8,12 (load col base)
    const float* Ap = A + (size_t)(bm + lr) * GEMM_K + lc;
    const float* Wp = W + (size_t)(bn + lr) * GEMM_K + lc;

    const int tx = tid & 15;          // 0..15 -> n sub-tile
    const int ty = tid >> 4;          // 0..15 -> m sub-tile

    float acc[8][8];
    #pragma unroll
    for (int i = 0; i < 8; i++)
        #pragma unroll
        for (int j = 0; j < 8; j++) acc[i][j] = 0.f;

    for (int kb = 0; kb < GEMM_K; kb += 16) {
        float4 a0 = *(const float4*)(Ap + kb);
        float4 a1 = *(const float4*)(Ap + (size_t)64 * GEMM_K + kb);
        float4 b0 = *(const float4*)(Wp + kb);
        float4 b1 = *(const float4*)(Wp + (size_t)64 * GEMM_K + kb);
        __syncthreads();
        As[lc+0][lr] = a0.x; As[lc+1][lr] = a0.y; As[lc+2][lr] = a0.z; As[lc+3][lr] = a0.w;
        As[lc+0][lr+64] = a1.x; As[lc+1][lr+64] = a1.y; As[lc+2][lr+64] = a1.z; As[lc+3][lr+64] = a1.w;
        Bs[lc+0][lr] = b0.x; Bs[lc+1][lr] = b0.y; Bs[lc+2][lr] = b0.z; Bs[lc+3][lr] = b0.w;
        Bs[lc+0][lr+64] = b1.x; Bs[lc+1][lr+64] = b1.y; Bs[lc+2][lr+64] = b1.z; Bs[lc+3][lr+64] = b1.w;
        __syncthreads();

        #pragma unroll
        for (int kk = 0; kk < 16; kk++) {
            float4 ra0 = *(const float4*)&As[kk][ty * 8];
            float4 ra1 = *(const float4*)&As[kk][ty * 8 + 4];
            float4 rb0 = *(const float4*)&Bs[kk][tx * 8];
            float4 rb1 = *(const float4*)&Bs[kk][tx * 8 + 4];
            float ra[8] = {ra0.x, ra0.y, ra0.z, ra0.w, ra1.x, ra1.y, ra1.z, ra1.w};
            float rb[8] = {rb0.x, rb0.y, rb0.z, rb0.w, rb1.x, rb1.y, rb1.z, rb1.w};
            #pragma unroll
            for (int i = 0; i < 8; i++)
                #pragma unroll
                for (int j = 0; j < 8; j++)
                    acc[i][j] = fmaf(ra[i], rb[j], acc[i][j]);
        }
    }

    #pragma unroll
    for (int i = 0; i < 8; i++) {
        const int m = bm + ty * 8 + i;
        #pragma unroll
        for (int j = 0; j < 8; j++) {
            const int n = bn + tx * 8 + j;
            float v = (acc[i][j] + bias[n]) * alpha;
            if (beta != 0.0f) v = fmaf(beta, Add[(size_t)m * GEMM_N + n], v);
            C[(size_t)m * GEMM_N + n] = v;
        }
    }
}

// ---------------------------------------------------------------------------
// Local attention with relative position bias.
// One CTA per (b, h): 256 threads. scores[l,r] = (q.k)/8 + q.rel_k[clip(r-l)+32]
// Quad mapping: thread = (l = tid>>2, cg = tid&3); phase1 r = 4j+cg (16 j),
// phase2 d = 4i+cg (16 i). smem strides chosen for conflict-free quad access.
// ---------------------------------------------------------------------------
__global__ __launch_bounds__(256)
void local_attn_kernel(const float* __restrict__ Q, const float* __restrict__ Kt,
                       const float* __restrict__ V, const float* __restrict__ RK,
                       float* __restrict__ O)
{
    extern __shared__ float sm[];
    float* qs = sm;                  // [64][68]
    float* kv = qs + 64 * 68;        // [64][68]  (k then reused for v)
    float* rk = kv + 64 * 68;        // [65][68]
    float* ps = rk + 65 * 68;        // [64][65]

    const int b = blockIdx.x >> 4;
    const int h = blockIdx.x & 15;
    const int tid = threadIdx.x;
    const int l = tid >> 2;
    const int cg = tid & 3;
    const size_t rowbase = ((size_t)b * 64 + l) * 1024 + h * 64;

    {   // stage q, k
        const int c0 = cg * 16;
        const float4* qsrc = (const float4*)(Q + rowbase + c0);
        const float4* ksrc = (const float4*)(Kt + rowbase + c0);
        #pragma unroll
        for (int t = 0; t < 4; t++) {
            float4 a = qsrc[t]; float4 bb = ksrc[t];
            int o = l * 68 + c0 + t * 4;
            qs[o+0]=a.x;  qs[o+1]=a.y;  qs[o+2]=a.z;  qs[o+3]=a.w;
            kv[o+0]=bb.x; kv[o+1]=bb.y; kv[o+2]=bb.z; kv[o+3]=bb.w;
        }
    }
    // stage rel_k table [65][64]
    for (int idx = tid; idx < 65 * 64; idx += 256) {
        int r = idx >> 6, c = idx & 63;
        rk[r * 68 + c] = RK[idx];
    }
    __syncthreads();

    // phase 1: scores + rel bias, q hoisted into registers
    float qreg[64];
    #pragma unroll
    for (int d = 0; d < 64; d++) qreg[d] = qs[l * 68 + d];

    float s[16];
    #pragma unroll
    for (int j = 0; j < 16; j++) {
        const int r = j * 4 + cg;
        int dlt = r - l;
        dlt = dlt < -32 ? -32 : (dlt > 32 ? 32 : dlt);
        const float* krow = kv + r * 68;
        const float* rrow = rk + (dlt + 32) * 68;
        float a0 = 0.f, a1 = 0.f;
        #pragma unroll
        for (int d = 0; d < 64; d++) {
            a0 = fmaf(qreg[d], krow[d], a0);
            a1 = fmaf(qreg[d], rrow[d], a1);
        }
        s[j] = a0 * 0.125f + a1;   // scale only the q.k term
    }

    // row softmax across quad (width-4 shfl reductions)
    float mx = s[0];
    #pragma unroll
    for (int j = 1; j < 16; j++) mx = fmaxf(mx, s[j]);
    mx = fmaxf(mx, __shfl_xor_sync(0xffffffffu, mx, 1));
    mx = fmaxf(mx, __shfl_xor_sync(0xffffffffu, mx, 2));
    float sum = 0.f;
    #pragma unroll
    for (int j = 0; j < 16; j++) { s[j] = __expf(s[j] - mx); sum += s[j]; }
    sum += __shfl_xor_sync(0xffffffffu, sum, 1);
    sum += __shfl_xor_sync(0xffffffffu, sum, 2);
    const float rinv = __frcp_rn(sum);
    #pragma unroll
    for (int j = 0; j < 16; j++) ps[l * 65 + j * 4 + cg] = s[j] * rinv;
    __syncthreads();   // all phase-1 reads of kv done

    {   // stage v over k's smem
        const int c0 = cg * 16;
        const float4* vsrc = (const float4*)(V + rowbase + c0);
        #pragma unroll
        for (int t = 0; t < 4; t++) {
            float4 a = vsrc[t];
            int o = l * 68 + c0 + t * 4;
            kv[o+0]=a.x; kv[o+1]=a.y; kv[o+2]=a.z; kv[o+3]=a.w;
        }
    }
    __syncthreads();

    // phase 2: out[l, 4i+cg] = sum_r p[l,r] * v[r, 4i+cg]
    float acc[16];
    #pragma unroll
    for (int i = 0; i < 16; i++) acc[i] = 0.f;
    for (int r = 0; r < 64; r++) {
        const float p = ps[l * 65 + r];
        const float* vrow = kv + r * 68;
        #pragma unroll
        for (int i = 0; i < 16; i++) acc[i] = fmaf(p, vrow[i * 4 + cg], acc[i]);
    }
    float* orow = O + rowbase;
    #pragma unroll
    for (int i = 0; i < 16; i++) orow[i * 4 + cg] = acc[i];
}

// ---------------------------------------------------------------------------
// Global branch: standard MHA, 8 heads of dim 128. One CTA per (b, g).
// ---------------------------------------------------------------------------
__global__ __launch_bounds__(256)
void global_attn_kernel(const float* __restrict__ Q, const float* __restrict__ Kt,
                        const float* __restrict__ V, float* __restrict__ O)
{
    extern __shared__ float sm[];
    float* qs = sm;                  // [64][132]
    float* kv = qs + 64 * 132;       // [64][132]  (k then v)
    float* ps = kv + 64 * 132;       // [64][65]

    const int b = blockIdx.x >> 3;
    const int g = blockIdx.x & 7;
    const int tid = threadIdx.x;
    const int l = tid >> 2;
    const int cg = tid & 3;
    const size_t rowbase = ((size_t)b * 64 + l) * 1024 + g * 128;

    {   // stage q, k (32 floats per thread)
        const int c0 = cg * 32;
        const float4* qsrc = (const float4*)(Q + rowbase + c0);
        const float4* ksrc = (const float4*)(Kt + rowbase + c0);
        #pragma unroll
        for (int t = 0; t < 8; t++) {
            float4 a = qsrc[t]; float4 bb = ksrc[t];
            int o = l * 132 + c0 + t * 4;
            qs[o]=a.x;  qs[o+1]=a.y;  qs[o+2]=a.z;  qs[o+3]=a.w;
            kv[o]=bb.x; kv[o+1]=bb.y; kv[o+2]=bb.z; kv[o+3]=bb.w;
        }
    }
    __syncthreads();

    // phase 1: scores, q cached in 32-reg chunks
    float s[16];
    #pragma unroll
    for (int j = 0; j < 16; j++) s[j] = 0.f;
    #pragma unroll
    for (int ch = 0; ch < 4; ch++) {
        const int d0 = ch * 32;
        float qreg[32];
        #pragma unroll
        for (int i = 0; i < 32; i++) qreg[i] = qs[l * 132 + d0 + i];
        #pragma unroll
        for (int j = 0; j < 16; j++) {
            const int r = j * 4 + cg;
            const float* krow = kv + r * 132 + d0;
            float a = 0.f;
            #pragma unroll
            for (int i = 0; i < 32; i++) a = fmaf(qreg[i], krow[i], a);
            s[j] += a;
        }
    }
    const float scale = 0.08838834764831845f;   // 1/sqrt(128)
    #pragma unroll
    for (int j = 0; j < 16; j++) s[j] *= scale;

    float mx = s[0];
    #pragma unroll
    for (int j = 1; j < 16; j++) mx = fmaxf(mx, s[j]);
    mx = fmaxf(mx, __shfl_xor_sync(0xffffffffu, mx, 1));
    mx = fmaxf(mx, __shfl_xor_sync(0xffffffffu, mx, 2));
    float sum = 0.f;
    #pragma unroll
    for (int j = 0; j < 16; j++) { s[j] = __expf(s[j] - mx); sum += s[j]; }
    sum += __shfl_xor_sync(0xffffffffu, sum, 1);
    sum += __shfl_xor_sync(0xffffffffu, sum, 2);
    const float rinv = __frcp_rn(sum);
    #pragma unroll
    for (int j = 0; j < 16; j++) ps[l * 65 + j * 4 + cg] = s[j] * rinv;
    __syncthreads();

    {   // stage v
        const int c0 = cg * 32;
        const float4* vsrc = (const float4*)(V + rowbase + c0);
        #pragma unroll
        for (int t = 0; t < 8; t++) {
            float4 a = vsrc[t];
            int o = l * 132 + c0 + t * 4;
            kv[o]=a.x; kv[o+1]=a.y; kv[o+2]=a.z; kv[o+3]=a.w;
        }
    }
    __syncthreads();

    // phase 2: out[l, 4i+cg] for i in 0..31
    float acc[32];
    #pragma unroll
    for (int i = 0; i < 32; i++) acc[i] = 0.f;
    for (int r = 0; r < 64; r++) {
        const float p = ps[l * 65 + r];
        const float* vrow = kv + r * 132;
        #pragma unroll
        for (int i = 0; i < 32; i++) acc[i] = fmaf(p, vrow[i * 4 + cg], acc[i]);
    }
    float* orow = O + rowbase;
    #pragma unroll
    for (int i = 0; i < 32; i++) orow[i * 4 + cg] = acc[i];
}

// ---------------------------------------------------------------------------
extern "C" void kernel_launch(void* const* d_in, const int* in_sizes, int n_in,
                              void* d_out, int out_size)
{
    const float* query   = (const float*)d_in[0];
    const float* key     = (const float*)d_in[1];
    const float* value   = (const float*)d_in[2];
    const float* Wq      = (const float*)d_in[3];
    const float* bq      = (const float*)d_in[4];
    const float* Wk      = (const float*)d_in[5];
    const float* bk      = (const float*)d_in[6];
    const float* Wv      = (const float*)d_in[7];
    const float* bv      = (const float*)d_in[8];
    const float* Wo      = (const float*)d_in[9];
    const float* bo      = (const float*)d_in[10];
    const float* rel_k   = (const float*)d_in[11];
    // d_in[12] = rel_v : looked up but unused in the reference
    const float* g_in_w  = (const float*)d_in[13];
    const float* g_in_b  = (const float*)d_in[14];
    const float* g_out_w = (const float*)d_in[15];
    const float* g_out_b = (const float*)d_in[16];
    float* out = (float*)d_out;

    void* symaddr = nullptr;
    cudaGetSymbolAddress(&symaddr, g_scratch);
    float* base = (float*)symaddr;
    float* qL   = base + 0 * ELEMS;
    float* kL   = base + 1 * ELEMS;
    float* vL   = base + 2 * ELEMS;
    float* qG   = base + 3 * ELEMS;
    float* kG   = base + 4 * ELEMS;
    float* vG   = base + 5 * ELEMS;
    float* locO = base + 6 * ELEMS;
    float* glbO = base + 7 * ELEMS;
    float* cmb  = base + 8 * ELEMS;

    const int smemL = (64 * 68 * 2 + 65 * 68 + 64 * 65) * 4;   // 69136 B
    const int smemG = (64 * 132 * 2 + 64 * 65) * 4;            // 84224 B
    cudaFuncSetAttribute(local_attn_kernel,
                         cudaFuncAttributeMaxDynamicSharedMemorySize, smemL);
    cudaFuncSetAttribute(global_attn_kernel,
                         cudaFuncAttributeMaxDynamicSharedMemorySize, smemG);

    dim3 gg(8, 128);   // N/128 x M/128

    // local projections
    sgemm_kernel<<<gg, 256>>>(query, Wq, bq, nullptr, qL, 1.f, 0.f);
    sgemm_kernel<<<gg, 256>>>(key,   Wk, bk, nullptr, kL, 1.f, 0.f);
    sgemm_kernel<<<gg, 256>>>(value, Wv, bv, nullptr, vL, 1.f, 0.f);
    // global in-proj (packed rows of g_in_w / g_in_b)
    sgemm_kernel<<<gg, 256>>>(query, g_in_w,           g_in_b,        nullptr, qG, 1.f, 0.f);
    sgemm_kernel<<<gg, 256>>>(key,   g_in_w + 1048576, g_in_b + 1024, nullptr, kG, 1.f, 0.f);
    sgemm_kernel<<<gg, 256>>>(value, g_in_w + 2097152, g_in_b + 2048, nullptr, vG, 1.f, 0.f);

    // attention cores
    local_attn_kernel <<<256 * 16, 256, smemL>>>(qL, kL, vL, rel_k, locO);
    global_attn_kernel<<<256 * 8,  256, smemG>>>(qG, kG, vG, glbO);

    // cmb = 0.3*(glbO @ g_out_w^T + g_out_b) + 0.7*locO   (combine fused in epilogue)
    sgemm_kernel<<<gg, 256>>>(glbO, g_out_w, g_out_b, locO, cmb, 0.3f, 0.7f);
    // out = cmb @ Wo^T + bo
    sgemm_kernel<<<gg, 256>>>(cmb, Wo, bo, nullptr, out, 1.f, 0.f);
}